// round 10
// baseline (speedup 1.0000x reference)
#include <cuda_runtime.h>

#define NT 512
#define CC 66
#define TT 100
#define JJ 22
#define HH 8
#define HD 64

// smem float offsets (contiguous W region reused by phase1/3 scratch)
#define OFF_SP   0        // sp   [66][100]   6600
#define OFF_TPT  6600     // tpT  [100][68]   6800
#define OFF_COMB 13400    // comb [104][68]   7072
#define OFF_W1   20472    // 4352
#define OFF_W2   24824    // 6400
#define OFF_W3   31224    // 6656
#define OFF_W4   37880    // 6400
#define OFF_STB  44280    // 7200
#define OFF_ASM  51480    // 484
#define OFF_RED  51964    // 832
#define SMEM_FLOATS 52796

__device__ __forceinline__ unsigned long long pk2(float lo, float hi) {
    unsigned long long r;
    asm("mov.b64 %0, {%1, %2};" : "=l"(r) : "f"(lo), "f"(hi));
    return r;
}
__device__ __forceinline__ void upk2(float& lo, float& hi, unsigned long long v) {
    asm("mov.b64 {%0, %1}, %2;" : "=f"(lo), "=f"(hi) : "l"(v));
}
__device__ __forceinline__ void fma2(unsigned long long& acc, unsigned long long a,
                                     unsigned long long b) {
    asm("fma.rn.f32x2 %0, %1, %2, %0;" : "+l"(acc) : "l"(a), "l"(b));
}

// ---------- 4x4 tile, f32x2. Caller guarantees t < ceil(M/4)*Nt ----------
__device__ __forceinline__ void gemm44(
    const float* __restrict__ A, const int lda,
    const float* __restrict__ B, const int ldb,
    float* __restrict__ C, const int ldc,
    const int Nt, const int K,
    const float* __restrict__ biasM, const float* __restrict__ biasN,
    const float scale, const bool accum, const int t)
{
    const int mt = t / Nt;
    const int m0 = mt << 2;
    const int n0 = (t - mt * Nt) << 2;

    unsigned long long acc[2][4];
    #pragma unroll
    for (int i = 0; i < 2; i++)
        #pragma unroll
        for (int j = 0; j < 4; j++) acc[i][j] = 0ull;

    const float* Ap = A + m0;
    const float* Bp = B + n0;
    #pragma unroll 2
    for (int k = 0; k < K; ++k) {
        const float4 av = *(const float4*)Ap;
        const float4 bv = *(const float4*)Bp;
        Ap += lda; Bp += ldb;
        const unsigned long long ap0 = pk2(av.x, av.y);
        const unsigned long long ap1 = pk2(av.z, av.w);
        const unsigned long long b0 = pk2(bv.x, bv.x);
        const unsigned long long b1 = pk2(bv.y, bv.y);
        const unsigned long long b2 = pk2(bv.z, bv.z);
        const unsigned long long b3 = pk2(bv.w, bv.w);
        fma2(acc[0][0], ap0, b0); fma2(acc[1][0], ap1, b0);
        fma2(acc[0][1], ap0, b1); fma2(acc[1][1], ap1, b1);
        fma2(acc[0][2], ap0, b2); fma2(acc[1][2], ap1, b2);
        fma2(acc[0][3], ap0, b3); fma2(acc[1][3], ap1, b3);
    }

    float bn[4] = {0.f, 0.f, 0.f, 0.f};
    if (biasN) { bn[0] = biasN[n0]; bn[1] = biasN[n0+1]; bn[2] = biasN[n0+2]; bn[3] = biasN[n0+3]; }
    #pragma unroll
    for (int p = 0; p < 2; p++) {
        float lo[4], hi[4];
        #pragma unroll
        for (int j = 0; j < 4; j++) upk2(lo[j], hi[j], acc[p][j]);
        const int mA = m0 + (p << 1);
        float bmA = 0.f, bmB = 0.f;
        if (biasM) { bmA = biasM[mA]; bmB = biasM[mA + 1]; }
        float4 rA, rB;
        rA.x = fmaf(lo[0], scale, bmA + bn[0]);
        rA.y = fmaf(lo[1], scale, bmA + bn[1]);
        rA.z = fmaf(lo[2], scale, bmA + bn[2]);
        rA.w = fmaf(lo[3], scale, bmA + bn[3]);
        rB.x = fmaf(hi[0], scale, bmB + bn[0]);
        rB.y = fmaf(hi[1], scale, bmB + bn[1]);
        rB.z = fmaf(hi[2], scale, bmB + bn[2]);
        rB.w = fmaf(hi[3], scale, bmB + bn[3]);
        float* cA = C + mA * ldc + n0;
        float* cB = cA + ldc;
        if (accum) {
            const float4 oA = *(const float4*)cA;
            const float4 oB = *(const float4*)cB;
            rA.x += oA.x; rA.y += oA.y; rA.z += oA.z; rA.w += oA.w;
            rB.x += oB.x; rB.y += oB.y; rB.z += oB.z; rB.w += oB.w;
        }
        *(float4*)cA = rA;
        *(float4*)cB = rB;
    }
}

// ---------- 8x4 tile, f32x2. Caller guarantees t < ceil(M/8)*Nt ----------
__device__ __forceinline__ void gemm84(
    const float* __restrict__ A, const int lda,
    const float* __restrict__ B, const int ldb,
    float* __restrict__ C, const int ldc,
    const int Nt, const int K,
    const float* __restrict__ biasM, const float* __restrict__ biasN,
    const float scale, const bool accum, const int t)
{
    const int mt = t / Nt;
    const int m0 = mt << 3;
    const int n0 = (t - mt * Nt) << 2;

    unsigned long long acc[4][4];
    #pragma unroll
    for (int i = 0; i < 4; i++)
        #pragma unroll
        for (int j = 0; j < 4; j++) acc[i][j] = 0ull;

    const float* Ap = A + m0;
    const float* Bp = B + n0;
    #pragma unroll 2
    for (int k = 0; k < K; ++k) {
        const float4 a0 = *(const float4*)Ap;
        const float4 a1 = *(const float4*)(Ap + 4);
        const float4 bv = *(const float4*)Bp;
        Ap += lda; Bp += ldb;
        const unsigned long long ap0 = pk2(a0.x, a0.y);
        const unsigned long long ap1 = pk2(a0.z, a0.w);
        const unsigned long long ap2 = pk2(a1.x, a1.y);
        const unsigned long long ap3 = pk2(a1.z, a1.w);
        const unsigned long long b0 = pk2(bv.x, bv.x);
        const unsigned long long b1 = pk2(bv.y, bv.y);
        const unsigned long long b2 = pk2(bv.z, bv.z);
        const unsigned long long b3 = pk2(bv.w, bv.w);
        fma2(acc[0][0], ap0, b0); fma2(acc[1][0], ap1, b0);
        fma2(acc[2][0], ap2, b0); fma2(acc[3][0], ap3, b0);
        fma2(acc[0][1], ap0, b1); fma2(acc[1][1], ap1, b1);
        fma2(acc[2][1], ap2, b1); fma2(acc[3][1], ap3, b1);
        fma2(acc[0][2], ap0, b2); fma2(acc[1][2], ap1, b2);
        fma2(acc[2][2], ap2, b2); fma2(acc[3][2], ap3, b2);
        fma2(acc[0][3], ap0, b3); fma2(acc[1][3], ap1, b3);
        fma2(acc[2][3], ap2, b3); fma2(acc[3][3], ap3, b3);
    }

    float bn[4] = {0.f, 0.f, 0.f, 0.f};
    if (biasN) { bn[0] = biasN[n0]; bn[1] = biasN[n0+1]; bn[2] = biasN[n0+2]; bn[3] = biasN[n0+3]; }
    #pragma unroll
    for (int i2 = 0; i2 < 4; i2++) {
        float lo[4], hi[4];
        #pragma unroll
        for (int j = 0; j < 4; j++) upk2(lo[j], hi[j], acc[i2][j]);
        const int mA = m0 + (i2 << 1);
        float bmA = 0.f, bmB = 0.f;
        if (biasM) { bmA = biasM[mA]; bmB = biasM[mA + 1]; }
        float4 rA, rB;
        rA.x = fmaf(lo[0], scale, bmA + bn[0]);
        rA.y = fmaf(lo[1], scale, bmA + bn[1]);
        rA.z = fmaf(lo[2], scale, bmA + bn[2]);
        rA.w = fmaf(lo[3], scale, bmA + bn[3]);
        rB.x = fmaf(hi[0], scale, bmB + bn[0]);
        rB.y = fmaf(hi[1], scale, bmB + bn[1]);
        rB.z = fmaf(hi[2], scale, bmB + bn[2]);
        rB.w = fmaf(hi[3], scale, bmB + bn[3]);
        float* cA = C + mA * ldc + n0;
        float* cB = cA + ldc;
        if (accum) {
            const float4 oA = *(const float4*)cA;
            const float4 oB = *(const float4*)cB;
            rA.x += oA.x; rA.y += oA.y; rA.z += oA.z; rA.w += oA.w;
            rB.x += oB.x; rB.y += oB.y; rB.z += oB.z; rB.w += oB.w;
        }
        *(float4*)cA = rA;
        *(float4*)cB = rB;
    }
}

// stage [rows][64] head-slice of a [rows][512] weight matrix
__device__ __forceinline__ void stage_w(float* __restrict__ dst, const float* __restrict__ src,
                                        const int rows, const int ho, int i, const int n)
{
    const int total = rows << 6;
    for (; i < total; i += n)
        dst[i] = src[(i >> 6) * 512 + ho + (i & 63)];
}
// st_wo slice [64][66] -> dst[64][68], zero pad cols
__device__ __forceinline__ void stage_wo66(float* __restrict__ dst, const float* __restrict__ src,
                                           const int ho, int i, const int n)
{
    for (; i < 64 * 68; i += n) {
        const int d = i / 68, c = i - d * 68;
        dst[i] = (c < CC) ? src[(ho + d) * CC + c] : 0.f;
    }
}
// ts_wo slice [64][100] (contiguous)
__device__ __forceinline__ void stage_wo100(float* __restrict__ dst, const float* __restrict__ src,
                                            const int ho, int i, const int n)
{
    for (; i < 64 * TT; i += n) dst[i] = src[ho * TT + i];
}

// two-level softmax over rows (k) for each column q of M[k][q]. All NT threads enter.
__device__ __forceinline__ void softmax2(float* __restrict__ M, const int ld,
                                         const int R, const int Qn,
                                         float* __restrict__ red, const int tid)
{
    const int w = tid >> 5, l = tid & 31;
    const int chunk = w & 3;
    const int quarter = w >> 2;
    const int q = (chunk << 5) + l;
    const int rlo = (R * quarter) >> 2;
    const int rhi = (R * (quarter + 1)) >> 2;
    const bool act = (q < Qn);

    float mx = -1e30f;
    if (act) for (int r = rlo; r < rhi; r++) mx = fmaxf(mx, M[r * ld + q]);
    if (act) red[quarter * 104 + q] = mx;
    __syncthreads();
    float gm = 0.f;
    if (act) gm = fmaxf(fmaxf(red[q], red[104 + q]), fmaxf(red[208 + q], red[312 + q]));
    float s = 0.f;
    if (act) {
        for (int r = rlo; r < rhi; r++) {
            const float e = __expf(M[r * ld + q] - gm);
            M[r * ld + q] = e; s += e;
        }
    }
    __syncthreads();
    if (act) red[416 + quarter * 104 + q] = s;
    __syncthreads();
    if (act) {
        const float inv = 1.f / (red[416 + q] + red[520 + q] + red[624 + q] + red[728 + q]);
        for (int r = rlo; r < rhi; r++) M[r * ld + q] *= inv;
    }
}

__global__ __launch_bounds__(NT, 1)
void fused_kernel(
    const float* __restrict__ x,
    const float* __restrict__ adj_mask,
    const float* __restrict__ s_adj,
    const float* __restrict__ traj_mask,
    const float* __restrict__ t_adj,
    const float* __restrict__ st_wq, const float* __restrict__ st_bq,
    const float* __restrict__ st_wk, const float* __restrict__ st_bk,
    const float* __restrict__ st_wv, const float* __restrict__ st_bv,
    const float* __restrict__ st_wo, const float* __restrict__ st_bo,
    const float* __restrict__ ts_wq, const float* __restrict__ ts_bq,
    const float* __restrict__ ts_wk, const float* __restrict__ ts_bk,
    const float* __restrict__ ts_wv, const float* __restrict__ ts_bv,
    const float* __restrict__ ts_wo, const float* __restrict__ ts_bo,
    const float* __restrict__ ln_alpha, const float* __restrict__ ln_beta,
    const float* __restrict__ fc_w, const float* __restrict__ fc_b,
    float* __restrict__ out)
{
    extern __shared__ float S[];
    float* SP   = S + OFF_SP;
    float* TPT  = S + OFF_TPT;
    float* COMB = S + OFF_COMB;
    float* W1   = S + OFF_W1;
    float* W2   = S + OFF_W2;
    float* W3   = S + OFF_W3;
    float* W4   = S + OFF_W4;
    float* STB  = S + OFF_STB;
    float* ASM  = S + OFF_ASM;
    float* RED  = S + OFF_RED;

    const int b   = blockIdx.x;
    const int tid = threadIdx.x;
    const float* xb = x + (size_t)b * (CC * TT);

    // ================= phase 1 =================
    {
        float* xs = W1;            // [66][100]  scratch
        float* Ms = W1 + 6600;     // [100][100] scratch
        for (int i = tid; i < CC * TT; i += NT) xs[i] = xb[i];
        for (int i = tid; i < TT * TT; i += NT) Ms[i] = t_adj[i] * traj_mask[i];
        for (int i = tid; i < JJ * JJ; i += NT) {
            const int v = i / JJ, j = i % JJ;
            float dv = 0.f, dj = 0.f;
            for (int k = 0; k < JJ; k++) { dv += adj_mask[v * JJ + k]; dj += adj_mask[j * JJ + k]; }
            const float iv = dv > 0.f ? rsqrtf(dv) : 0.f;
            const float ij = dj > 0.f ? rsqrtf(dj) : 0.f;
            ASM[i] = s_adj[i] * adj_mask[i] * iv * ij;
        }
        __syncthreads();
        for (int i = tid; i < CC * TT; i += NT) {
            const int c = i / TT, t = i % TT;
            const int v = c / 3, dd = c % 3;
            float acc = 0.f;
            #pragma unroll
            for (int j = 0; j < JJ; j++)
                acc = fmaf(ASM[v * JJ + j], xs[(j * 3 + dd) * TT + t], acc);
            SP[i] = acc;
        }
        for (int i = tid; i < TT * 68; i += NT) {
            const int f = i / 68, c = i % 68;
            if (c >= CC) { TPT[i] = 0.f; continue; }
            const float4* mr = (const float4*)(Ms + f * TT);
            const float4* xr = (const float4*)(xs + c * TT);
            unsigned long long a01 = 0ull, a23 = 0ull;
            #pragma unroll 5
            for (int k = 0; k < TT / 4; k++) {
                const float4 m4 = mr[k], x4 = xr[k];
                fma2(a01, pk2(m4.x, m4.y), pk2(x4.x, x4.y));
                fma2(a23, pk2(m4.z, m4.w), pk2(x4.z, x4.w));
            }
            float l0, h0, l1, h1;
            upk2(l0, h0, a01); upk2(l1, h1, a23);
            TPT[i] = (l0 + h0) + (l1 + h1);
        }
        for (int i = tid; i < 104 * 68; i += NT) {
            const int t = i / 68, c = i % 68;
            COMB[i] = (t < TT && c < CC) ? (st_bo[c] + ts_bo[t]) : 0.f;
        }
        __syncthreads();
        // preload head 0: wq_st -> W1, wk_st -> W3
        stage_w(W1, st_wq, CC, 0, tid, NT);
        stage_w(W3, st_wk, TT, 0, tid, NT);
        __syncthreads();
    }

    for (int h = 0; h < HH; h++) {
        const int ho  = h << 6;
        const int ho2 = ((h + 1) & 7) << 6;

        // S1: Qst = W1(wq_st) x SP -> W2 [64][100]   (4x4, 400 thr)
        //     | stage wv_st -> W4 (96 thr)
        if (tid < 400)       gemm44(W1, 64, SP, 100, W2, 100, 25, CC, st_bq + ho, nullptr, 1.f, false, tid);
        else if (tid >= 416) stage_w(W4, st_wv, TT, ho, tid - 416, 96);
        __syncthreads();
        // S2: Kst = W3(wk_st) x TPT -> W1 [64][68]   (4x4, 272 thr)
        if (tid < 272)       gemm44(W3, 64, TPT, 68, W1, 68, 17, TT, st_bk + ho, nullptr, 1.f, false, tid);
        __syncthreads();
        // S3: ST_st = W1(Kst) x W2(Qst) -> STB [72][100]  (8x4, 225 thr, K=64, scale)
        //     || Vst = TPT x W4(wv_st) -> W3 [68][64]     (4x4, 272 thr, K=100)
        if (tid < 225)       gemm84(W1, 68, W2, 100, STB, 100, 25, HD, nullptr, nullptr, 0.125f, false, tid);
        else if (tid >= 240 && tid < 240 + 272)
                             gemm44(TPT, 68, W4, 64, W3, 64, 16, TT, nullptr, st_bv + ho, 1.f, false, tid - 240);
        __syncthreads();
        // S4: softmax over c (66 rows), 100 cols
        softmax2(STB, 100, CC, TT, RED, tid);
        __syncthreads();
        // S5: Ost = W3(Vst) x STB -> W2 [64][100]    (4x4, 400 thr, K=66)
        //     | stage wo_st -> W1 (96 thr)
        if (tid < 400)       gemm44(W3, 64, STB, 100, W2, 100, 25, CC, nullptr, nullptr, 1.f, false, tid);
        else if (tid >= 416) stage_wo66(W1, st_wo, ho, tid - 416, 96);
        __syncthreads();
        // S6: COMB[t][c] += W2(Ost)^T x W1(wo_st)    (4x4, 425 thr, K=64)
        //     | stage wq_ts -> W4 (64 thr)
        if (tid < 425)       gemm44(W2, 100, W1, 68, COMB, 68, 17, HD, nullptr, nullptr, 1.f, true, tid);
        else if (tid >= 448) stage_w(W4, ts_wq, TT, ho, tid - 448, 64);
        __syncthreads();

        // T1: Qts = W4(wq_ts) x TPT -> W1 [64][68]   (4x4, 272 thr, K=100)
        //     | stage wk_ts -> W3, wv_ts -> W2 (224 thr)
        if (tid < 272)       gemm44(W4, 64, TPT, 68, W1, 68, 17, TT, ts_bq + ho, nullptr, 1.f, false, tid);
        else if (tid >= 288) {
            for (int i = tid - 288; i < 2 * 4224; i += 224) {
                if (i < 4224) W3[i] = ts_wk[(i >> 6) * 512 + ho + (i & 63)];
                else { const int j = i - 4224; W2[j] = ts_wv[(j >> 6) * 512 + ho + (j & 63)]; }
            }
        }
        __syncthreads();
        // T2a: Kts = W3(wk_ts) x SP -> W4 [64][100]  (4x4, 400 thr, K=66)
        if (tid < 400)       gemm44(W3, 64, SP, 100, W4, 100, 25, CC, ts_bk + ho, nullptr, 1.f, false, tid);
        __syncthreads();
        // T2b: Vts = SP x W2(wv_ts) -> W3 [100][64]  (4x4, 400 thr, K=66)
        if (tid < 400)       gemm44(SP, 100, W2, 64, W3, 64, 16, CC, nullptr, ts_bv + ho, 1.f, false, tid);
        __syncthreads();
        // T3: ST_ts = W4(Kts) x W1(Qts) -> STB [100][68]  (4x4, 425 thr, K=64, scale)
        //     | stage wo_ts -> W2 (64 thr)
        if (tid < 425)       gemm44(W4, 100, W1, 68, STB, 68, 17, HD, nullptr, nullptr, 0.125f, false, tid);
        else if (tid >= 448) stage_wo100(W2, ts_wo, ho, tid - 448, 64);
        __syncthreads();
        // T4: softmax over t (100 rows), 66 cols
        softmax2(STB, 68, TT, CC, RED, tid);
        __syncthreads();
        // T5: Ots = W3(Vts) x STB -> W4 [64][68]     (4x4, 272 thr, K=100)
        //     | stage next wq_st -> W1 (224 thr)
        if (tid < 272)       gemm44(W3, 64, STB, 68, W4, 68, 17, TT, nullptr, nullptr, 1.f, false, tid);
        else if (tid >= 288) stage_w(W1, st_wq, CC, ho2, tid - 288, 224);
        __syncthreads();
        // T6: COMB[t][c] += W2(wo_ts)^T x W4(Ots)    (4x4, 425 thr, K=64)
        //     | stage next wk_st -> W3 (64 thr)
        if (tid < 425)       gemm44(W2, 100, W4, 68, COMB, 68, 17, HD, nullptr, nullptr, 1.f, true, tid);
        else if (tid >= 448) stage_w(W3, st_wk, TT, ho2, tid - 448, 64);
        __syncthreads();
    }

    // ================= phase 3 =================
    {
        float* fw = W1;            // [100][100] spans W1+W2
        for (int i = tid; i < TT * TT; i += NT) fw[i] = fc_w[i];
        if (tid < TT) {
            const int t = tid;
            float mean = 0.f;
            for (int c = 0; c < CC; c++) mean += COMB[t * 68 + c];
            mean *= (1.f / 66.f);
            float var = 0.f;
            for (int c = 0; c < CC; c++) {
                const float v = COMB[t * 68 + c] - mean;
                var = fmaf(v, v, var);
            }
            var *= (1.f / 66.f);
            const float inv = rsqrtf(var + 1e-5f);
            for (int c = 0; c < CC; c++) {
                const float y = (COMB[t * 68 + c] - mean) * inv * ln_alpha[c] + ln_beta[c];
                SP[c * TT + t] = y + xb[c * TT + t];
            }
        }
        __syncthreads();
        float* outb = out + (size_t)b * (CC * TT);
        for (int i = tid; i < CC * TT; i += NT) {
            const int c = i / TT, f = i % TT;
            const float4* zr = (const float4*)(SP + c * TT);
            const float4* fr = (const float4*)(fw + f * TT);
            unsigned long long a01 = 0ull, a23 = 0ull;
            #pragma unroll 5
            for (int k = 0; k < TT / 4; k++) {
                const float4 z4 = zr[k], f4 = fr[k];
                fma2(a01, pk2(z4.x, z4.y), pk2(f4.x, f4.y));
                fma2(a23, pk2(z4.z, z4.w), pk2(f4.z, f4.w));
            }
            float l0, h0, l1, h1;
            upk2(l0, h0, a01); upk2(l1, h1, a23);
            outb[i] = tanhf(fc_b[f] + (l0 + h0) + (l1 + h1));
        }
    }
}

extern "C" void kernel_launch(void* const* d_in, const int* in_sizes, int n_in,
                              void* d_out, int out_size) {
    const float* x         = (const float*)d_in[0];
    const float* adj_mask  = (const float*)d_in[1];
    const float* s_adj     = (const float*)d_in[2];
    const float* traj_mask = (const float*)d_in[3];
    const float* t_adj     = (const float*)d_in[4];
    const float* st_wq = (const float*)d_in[5];  const float* st_bq = (const float*)d_in[6];
    const float* st_wk = (const float*)d_in[7];  const float* st_bk = (const float*)d_in[8];
    const float* st_wv = (const float*)d_in[9];  const float* st_bv = (const float*)d_in[10];
    const float* st_wo = (const float*)d_in[11]; const float* st_bo = (const float*)d_in[12];
    const float* ts_wq = (const float*)d_in[13]; const float* ts_bq = (const float*)d_in[14];
    const float* ts_wk = (const float*)d_in[15]; const float* ts_bk = (const float*)d_in[16];
    const float* ts_wv = (const float*)d_in[17]; const float* ts_bv = (const float*)d_in[18];
    const float* ts_wo = (const float*)d_in[19]; const float* ts_bo = (const float*)d_in[20];
    const float* ln_alpha = (const float*)d_in[21];
    const float* ln_beta  = (const float*)d_in[22];
    const float* fc_w     = (const float*)d_in[23];
    const float* fc_b     = (const float*)d_in[24];
    float* out = (float*)d_out;

    const int B = in_sizes[0] / (CC * TT);
    const size_t smem = (size_t)SMEM_FLOATS * sizeof(float);
    cudaFuncSetAttribute(fused_kernel, cudaFuncAttributeMaxDynamicSharedMemorySize, (int)smem);

    fused_kernel<<<B, NT, smem>>>(
        x, adj_mask, s_adj, traj_mask, t_adj,
        st_wq, st_bq, st_wk, st_bk, st_wv, st_bv, st_wo, st_bo,
        ts_wq, ts_bq, ts_wk, ts_bk, ts_wv, ts_bv, ts_wo, ts_bo,
        ln_alpha, ln_beta, fc_w, fc_b, out);
}